// round 11
// baseline (speedup 1.0000x reference)
#include <cuda_runtime.h>
#include <math.h>

// ---------------------------------------------------------------------------
// Compile-time DCT-II matrix (matches reference: PI = 3.1415926 truncated).
// Entries are +/- 0.5*cos(k*pi/16) and sqrt(1/8); fold error vs reference
// < 4e-7. Function-local constexpr => every CD.v[const][const] becomes an
// FFMA immediate operand (no LDS/LDC in the hot loop).
// ---------------------------------------------------------------------------
struct DCTTab { float v[8][8]; };

__host__ __device__ constexpr DCTTab make_dct() {
    const float ck[9] = {0.5f,        0.49039264f, 0.46193977f, 0.41573481f,
                         0.35355339f, 0.27778512f, 0.19134172f, 0.09754516f,
                         0.0f};
    DCTTab t{};
    for (int i = 0; i < 8; i++) {
        for (int j = 0; j < 8; j++) {
            if (i == 0) { t.v[i][j] = 0.35355339f; continue; }  // sqrt(1/8)
            int a = (i * (2 * j + 1)) % 32;
            float s = 1.0f;
            if (a > 16) a = 32 - a;                  // cos(2pi-x) =  cos(x)
            if (a > 8)  { a = 16 - a; s = -1.0f; }   // cos(pi-x)  = -cos(x)
            t.v[i][j] = s * ck[a];
        }
    }
    return t;
}

__device__ __forceinline__ float gelu_exact(float x) {
    return 0.5f * x * (1.0f + erff(x * 0.70710678f));
}

// ---------------------------------------------------------------------------
// Single fused kernel = R6's measured-fastest body (80.3us) + low-register
// phased MLP prologue. Cross-round evidence:
//   R6 body: regs=168, xv[64] in registers, NO smem stash, NO (128,4) cap
//            -> 80.3us @ occ 16.4%.
//   R8/R9:   capped (128,4) + smem x-stash -> 92-93us. The reg squeeze +
//            stash latency chains cost more than the occupancy gain; regs/
//            thread binds warps/SM regardless of CTA shape, so the cap only
//            hurt ILP.
// Therefore: NO min-blocks clause, NO x stash. The MLP prologue keeps only
// scalars live and is dead before the body, so allocation = body's 168.
// ---------------------------------------------------------------------------
__global__ void __launch_bounds__(128)
fused_dct_kernel(const float* __restrict__ x,
                 float* __restrict__ lo,
                 float* __restrict__ hi,
                 const float* __restrict__ noise,
                 const float* __restrict__ qmat,
                 const float* __restrict__ qmw,
                 const float* __restrict__ w1, const float* __restrict__ b1,
                 const float* __restrict__ w2, const float* __restrict__ b2,
                 const float* __restrict__ w3, const float* __restrict__ b3) {
    constexpr DCTTab CD = make_dct();

    __shared__ __align__(16) float sq[64];
    __shared__ float s_h1[16], s_h2[16], s_nr[18], s_coef[16];

    const int t = threadIdx.x;

    // ================= prologue: learned quant matrix (MLP) ================
    if (t < 16) s_h1[t] = gelu_exact(noise[0] * w1[t] + b1[t]);
    __syncthreads();
    if (t < 16) {
        float s = b2[t];
#pragma unroll
        for (int j = 0; j < 16; j++) s += s_h1[j] * w2[j * 16 + t];
        s_h2[t] = gelu_exact(s);
    }
    __syncthreads();
    if (t < 18) {
        float s = b3[t];
#pragma unroll
        for (int j = 0; j < 16; j++) s += s_h2[j] * w3[j * 18 + t];
        s_nr[t] = s;
    }
    __syncthreads();
    if (t == 0) {
        float wmax = qmw[0];
#pragma unroll
        for (int i = 1; i < 16; i++) wmax = fmaxf(wmax, qmw[i]);
        float esum = 0.0f;
#pragma unroll
        for (int i = 0; i < 16; i++) esum += expf(qmw[i] - wmax);
        float inv = 1.0f / esum;
        float nr0 = s_nr[0], nr1 = s_nr[1];
#pragma unroll
        for (int i = 0; i < 16; i++)
            s_coef[i] = (expf(qmw[i] - wmax) * inv * nr0 + nr1) * s_nr[2 + i];
    }
    __syncthreads();
    if (t < 64) {
        float acc = 0.0f;
#pragma unroll
        for (int i = 0; i < 16; i++) acc += s_coef[i] * qmat[i * 64 + t];
        sq[t] = acc;
    }
    __syncthreads();
    // ======================================================================

    // ---- block geometry: one thread per 8x8 block ----
    const int b   = blockIdx.x * 128 + t;       // global 8x8-block id
    const int img = b >> 6;
    const int by  = (b >> 3) & 7;
    const int bx  = b & 7;
    const long base = (long)img * 4096 + by * 512 + bx * 8;  // floats

    // ---- load 8x8 block (kept in registers through the whole pipeline) ----
    float xv[64];
#pragma unroll
    for (int r = 0; r < 8; r++) {
        const float4* p = reinterpret_cast<const float4*>(x + base + r * 64);
        float4 a = p[0], c = p[1];
        xv[r * 8 + 0] = a.x; xv[r * 8 + 1] = a.y; xv[r * 8 + 2] = a.z; xv[r * 8 + 3] = a.w;
        xv[r * 8 + 4] = c.x; xv[r * 8 + 5] = c.y; xv[r * 8 + 6] = c.z; xv[r * 8 + 7] = c.w;
    }

    // ---- row DCT: W[r][m] = sum_j x[r][j] * C[m][j] ----
    float w[64];
#pragma unroll
    for (int r = 0; r < 8; r++) {
#pragma unroll
        for (int m = 0; m < 8; m++) {
            float acc = 0.0f;
#pragma unroll
            for (int j = 0; j < 8; j++) acc = fmaf(xv[r * 8 + j], CD.v[m][j], acc);
            w[r * 8 + m] = acc;
        }
    }

    // ---- col DCT in place ----
#pragma unroll
    for (int c = 0; c < 8; c++) {
        float y[8];
#pragma unroll
        for (int r = 0; r < 8; r++) y[r] = w[r * 8 + c];
#pragma unroll
        for (int i = 0; i < 8; i++) {
            float acc = 0.0f;
#pragma unroll
            for (int r = 0; r < 8; r++) acc = fmaf(y[r], CD.v[i][r], acc);
            w[i * 8 + c] = acc;
        }
    }

    // ---- spectral mask (warp-uniform float4 smem broadcasts) ----
    const float4* sq4 = reinterpret_cast<const float4*>(sq);
#pragma unroll
    for (int k = 0; k < 16; k++) {
        float4 q = sq4[k];
        w[k * 4 + 0] *= q.x;
        w[k * 4 + 1] *= q.y;
        w[k * 4 + 2] *= q.z;
        w[k * 4 + 3] *= q.w;
    }

    // ---- col IDCT in place ----
#pragma unroll
    for (int c = 0; c < 8; c++) {
        float z[8];
#pragma unroll
        for (int i = 0; i < 8; i++) z[i] = w[i * 8 + c];
#pragma unroll
        for (int a = 0; a < 8; a++) {
            float acc = 0.0f;
#pragma unroll
            for (int i = 0; i < 8; i++) acc = fmaf(z[i], CD.v[i][a], acc);
            w[a * 8 + c] = acc;
        }
    }

    // ---- row IDCT + high = x - low + stores ----
#pragma unroll
    for (int r = 0; r < 8; r++) {
        float tt[8];
#pragma unroll
        for (int m = 0; m < 8; m++) tt[m] = w[r * 8 + m];

        float lv[8], hv[8];
#pragma unroll
        for (int bb = 0; bb < 8; bb++) {
            float acc = 0.0f;
#pragma unroll
            for (int m = 0; m < 8; m++) acc = fmaf(tt[m], CD.v[m][bb], acc);
            lv[bb] = acc;
            hv[bb] = xv[r * 8 + bb] - acc;
        }

        float4* lp = reinterpret_cast<float4*>(lo + base + r * 64);
        lp[0] = make_float4(lv[0], lv[1], lv[2], lv[3]);
        lp[1] = make_float4(lv[4], lv[5], lv[6], lv[7]);
        float4* hp = reinterpret_cast<float4*>(hi + base + r * 64);
        hp[0] = make_float4(hv[0], hv[1], hv[2], hv[3]);
        hp[1] = make_float4(hv[4], hv[5], hv[6], hv[7]);
    }
}

// ---------------------------------------------------------------------------
// Launch: metadata order = x, noise_level, qmat, qmat_weights, w1,b1,w2,b2,w3,b3
// d_out = [low (N floats) | high (N floats)]
// ---------------------------------------------------------------------------
extern "C" void kernel_launch(void* const* d_in, const int* in_sizes, int n_in,
                              void* d_out, int out_size) {
    const float* x     = (const float*)d_in[0];
    const float* noise = (const float*)d_in[1];
    const float* qmat  = (const float*)d_in[2];
    const float* qmw   = (const float*)d_in[3];
    const float* w1    = (const float*)d_in[4];
    const float* b1    = (const float*)d_in[5];
    const float* w2    = (const float*)d_in[6];
    const float* b2    = (const float*)d_in[7];
    const float* w3    = (const float*)d_in[8];
    const float* b3    = (const float*)d_in[9];

    const int N       = in_sizes[0];   // 33554432
    const int nblocks = N / 64;        // 524288 8x8 blocks
    const int grid    = nblocks / 128;

    float* lo = (float*)d_out;
    float* hi = lo + N;

    fused_dct_kernel<<<grid, 128>>>(x, lo, hi, noise, qmat, qmw,
                                    w1, b1, w2, b2, w3, b3);
}

// round 12
// speedup vs baseline: 1.0086x; 1.0086x over previous
#include <cuda_runtime.h>
#include <math.h>

// ---------------------------------------------------------------------------
// Compile-time DCT-II matrix (matches reference: PI = 3.1415926 truncated).
// Entries are +/- 0.5*cos(k*pi/16) and sqrt(1/8); fold error vs reference
// < 4e-7. Function-local constexpr => FFMA immediates, no LDS/LDC.
// ---------------------------------------------------------------------------
struct DCTTab { float v[8][8]; };

__host__ __device__ constexpr DCTTab make_dct() {
    const float ck[9] = {0.5f,        0.49039264f, 0.46193977f, 0.41573481f,
                         0.35355339f, 0.27778512f, 0.19134172f, 0.09754516f,
                         0.0f};
    DCTTab t{};
    for (int i = 0; i < 8; i++) {
        for (int j = 0; j < 8; j++) {
            if (i == 0) { t.v[i][j] = 0.35355339f; continue; }  // sqrt(1/8)
            int a = (i * (2 * j + 1)) % 32;
            float s = 1.0f;
            if (a > 16) a = 32 - a;                  // cos(2pi-x) =  cos(x)
            if (a > 8)  { a = 16 - a; s = -1.0f; }   // cos(pi-x)  = -cos(x)
            t.v[i][j] = s * ck[a];
        }
    }
    return t;
}

__device__ float g_lq[64];

__device__ __forceinline__ float gelu_exact(float x) {
    return 0.5f * x * (1.0f + erff(x * 0.70710678f));
}

// ---------------------------------------------------------------------------
// FAST phased setup kernel (64 threads, ~3us): replaces R6's slow redundant
// version (every thread redid the whole MLP -> long serial gmem chains).
// ---------------------------------------------------------------------------
__global__ void setup_kernel(const float* __restrict__ noise,
                             const float* __restrict__ qmat,
                             const float* __restrict__ qmw,
                             const float* __restrict__ w1, const float* __restrict__ b1,
                             const float* __restrict__ w2, const float* __restrict__ b2,
                             const float* __restrict__ w3, const float* __restrict__ b3) {
    __shared__ float s_h1[16], s_h2[16], s_nr[18], s_coef[16];
    const int t = threadIdx.x;  // 0..63

    if (t < 16) s_h1[t] = gelu_exact(noise[0] * w1[t] + b1[t]);
    __syncthreads();
    if (t < 16) {
        float s = b2[t];
#pragma unroll
        for (int j = 0; j < 16; j++) s += s_h1[j] * w2[j * 16 + t];
        s_h2[t] = gelu_exact(s);
    }
    __syncthreads();
    if (t < 18) {
        float s = b3[t];
#pragma unroll
        for (int j = 0; j < 16; j++) s += s_h2[j] * w3[j * 18 + t];
        s_nr[t] = s;
    }
    __syncthreads();
    if (t == 0) {
        float wmax = qmw[0];
#pragma unroll
        for (int i = 1; i < 16; i++) wmax = fmaxf(wmax, qmw[i]);
        float esum = 0.0f;
#pragma unroll
        for (int i = 0; i < 16; i++) esum += expf(qmw[i] - wmax);
        float inv = 1.0f / esum;
        float nr0 = s_nr[0], nr1 = s_nr[1];
#pragma unroll
        for (int i = 0; i < 16; i++)
            s_coef[i] = (expf(qmw[i] - wmax) * inv * nr0 + nr1) * s_nr[2 + i];
    }
    __syncthreads();
    {
        float acc = 0.0f;
#pragma unroll
        for (int i = 0; i < 16; i++) acc += s_coef[i] * qmat[i * 64 + t];
        g_lq[t] = acc;
    }
}

// ---------------------------------------------------------------------------
// Main kernel: one thread per 8x8 block.
// KEY CHANGE vs R6 (80.3us, 168 regs, 12 warps/SM): xv[64] is NOT held live.
// x is consumed during the row DCT and RE-READ at the end for high = x - low.
// The re-read is made an L2 HIT by storing lo/hi with __stcs (evict-first):
// R7 proved normal stores (268MB of allocations) flush x out of L2; with
// stores marked evict-first, x's reuse distance (~one thread lifetime,
// ~15-20MB of intervening fills) is far under the 126MB L2.
// Live set drops to w[64]+temps (~110 regs) -> ~5 CTAs/SM, ~20 warps.
// No __launch_bounds__ cap (R8: caps => local spills).
// ---------------------------------------------------------------------------
__global__ void __launch_bounds__(128)
dct_kernel(const float* __restrict__ x,
           float* __restrict__ lo,
           float* __restrict__ hi) {
    constexpr DCTTab CD = make_dct();

    __shared__ __align__(16) float sq[64];
    if (threadIdx.x < 64) sq[threadIdx.x] = g_lq[threadIdx.x];
    __syncthreads();

    const int t   = threadIdx.x;
    const int b   = blockIdx.x * 128 + t;       // global 8x8-block id
    const int img = b >> 6;
    const int by  = (b >> 3) & 7;
    const int bx  = b & 7;
    const long base  = (long)img * 4096 + by * 512 + bx * 8;  // floats
    const long base4 = base >> 2;                              // float4s

    const float4* xp = reinterpret_cast<const float4*>(x);

    // ---- load + row DCT fused: x lives 8 floats at a time ----
    float w[64];
#pragma unroll
    for (int r = 0; r < 8; r++) {
        float4 a = __ldg(xp + base4 + r * 16);
        float4 c = __ldg(xp + base4 + r * 16 + 1);
        float xr[8] = {a.x, a.y, a.z, a.w, c.x, c.y, c.z, c.w};
#pragma unroll
        for (int m = 0; m < 8; m++) {
            float acc = 0.0f;
#pragma unroll
            for (int j = 0; j < 8; j++) acc = fmaf(xr[j], CD.v[m][j], acc);
            w[r * 8 + m] = acc;
        }
    }

    // ---- col DCT in place ----
#pragma unroll
    for (int c = 0; c < 8; c++) {
        float y[8];
#pragma unroll
        for (int r = 0; r < 8; r++) y[r] = w[r * 8 + c];
#pragma unroll
        for (int i = 0; i < 8; i++) {
            float acc = 0.0f;
#pragma unroll
            for (int r = 0; r < 8; r++) acc = fmaf(y[r], CD.v[i][r], acc);
            w[i * 8 + c] = acc;
        }
    }

    // ---- spectral mask (warp-uniform float4 smem broadcasts) ----
    const float4* sq4 = reinterpret_cast<const float4*>(sq);
#pragma unroll
    for (int k = 0; k < 16; k++) {
        float4 q = sq4[k];
        w[k * 4 + 0] *= q.x;
        w[k * 4 + 1] *= q.y;
        w[k * 4 + 2] *= q.z;
        w[k * 4 + 3] *= q.w;
    }

    // ---- col IDCT in place ----
#pragma unroll
    for (int c = 0; c < 8; c++) {
        float z[8];
#pragma unroll
        for (int i = 0; i < 8; i++) z[i] = w[i * 8 + c];
#pragma unroll
        for (int a = 0; a < 8; a++) {
            float acc = 0.0f;
#pragma unroll
            for (int i = 0; i < 8; i++) acc = fmaf(z[i], CD.v[i][a], acc);
            w[a * 8 + c] = acc;
        }
    }

    // ---- row IDCT + L2-hit x re-read + high = x - low; __stcs stores ----
    float4* lp = reinterpret_cast<float4*>(lo);
    float4* hp = reinterpret_cast<float4*>(hi);
#pragma unroll
    for (int r = 0; r < 8; r++) {
        float tt[8];
#pragma unroll
        for (int m = 0; m < 8; m++) tt[m] = w[r * 8 + m];

        float lv[8];
#pragma unroll
        for (int bb = 0; bb < 8; bb++) {
            float acc = 0.0f;
#pragma unroll
            for (int m = 0; m < 8; m++) acc = fmaf(tt[m], CD.v[m][bb], acc);
            lv[bb] = acc;
        }

        float4 a = __ldg(xp + base4 + r * 16);
        float4 c = __ldg(xp + base4 + r * 16 + 1);

        __stcs(lp + base4 + r * 16,     make_float4(lv[0], lv[1], lv[2], lv[3]));
        __stcs(lp + base4 + r * 16 + 1, make_float4(lv[4], lv[5], lv[6], lv[7]));
        __stcs(hp + base4 + r * 16,
               make_float4(a.x - lv[0], a.y - lv[1], a.z - lv[2], a.w - lv[3]));
        __stcs(hp + base4 + r * 16 + 1,
               make_float4(c.x - lv[4], c.y - lv[5], c.z - lv[6], c.w - lv[7]));
    }
}

// ---------------------------------------------------------------------------
// Launch: metadata order = x, noise_level, qmat, qmat_weights, w1,b1,w2,b2,w3,b3
// d_out = [low (N floats) | high (N floats)]
// ---------------------------------------------------------------------------
extern "C" void kernel_launch(void* const* d_in, const int* in_sizes, int n_in,
                              void* d_out, int out_size) {
    const float* x     = (const float*)d_in[0];
    const float* noise = (const float*)d_in[1];
    const float* qmat  = (const float*)d_in[2];
    const float* qmw   = (const float*)d_in[3];
    const float* w1    = (const float*)d_in[4];
    const float* b1    = (const float*)d_in[5];
    const float* w2    = (const float*)d_in[6];
    const float* b2    = (const float*)d_in[7];
    const float* w3    = (const float*)d_in[8];
    const float* b3    = (const float*)d_in[9];

    const int N       = in_sizes[0];   // 33554432
    const int nblocks = N / 64;        // 524288 8x8 blocks
    const int grid    = nblocks / 128;

    float* lo = (float*)d_out;
    float* hi = lo + N;

    setup_kernel<<<1, 64>>>(noise, qmat, qmw, w1, b1, w2, b2, w3, b3);
    dct_kernel<<<grid, 128>>>(x, lo, hi);
}

// round 14
// speedup vs baseline: 1.1296x; 1.1200x over previous
#include <cuda_runtime.h>
#include <math.h>

// ---------------------------------------------------------------------------
// Compile-time DCT-II matrix (matches reference: PI = 3.1415926 truncated).
// Entries are +/- 0.5*cos(k*pi/16) and sqrt(1/8); fold error vs reference
// < 4e-7. Function-local constexpr => FFMA immediates, no LDS/LDC.
// ---------------------------------------------------------------------------
struct DCTTab { float v[8][8]; };

__host__ __device__ constexpr DCTTab make_dct() {
    const float ck[9] = {0.5f,        0.49039264f, 0.46193977f, 0.41573481f,
                         0.35355339f, 0.27778512f, 0.19134172f, 0.09754516f,
                         0.0f};
    DCTTab t{};
    for (int i = 0; i < 8; i++) {
        for (int j = 0; j < 8; j++) {
            if (i == 0) { t.v[i][j] = 0.35355339f; continue; }  // sqrt(1/8)
            int a = (i * (2 * j + 1)) % 32;
            float s = 1.0f;
            if (a > 16) a = 32 - a;                  // cos(2pi-x) =  cos(x)
            if (a > 8)  { a = 16 - a; s = -1.0f; }   // cos(pi-x)  = -cos(x)
            t.v[i][j] = s * ck[a];
        }
    }
    return t;
}

__device__ float g_lq[64];

__device__ __forceinline__ float gelu_exact(float x) {
    return 0.5f * x * (1.0f + erff(x * 0.70710678f));
}

// ---------------------------------------------------------------------------
// Fast phased setup kernel (64 threads, ~3us). Triggers the dependent main
// kernel's gate immediately after g_lq is written.
// ---------------------------------------------------------------------------
__global__ void setup_kernel(const float* __restrict__ noise,
                             const float* __restrict__ qmat,
                             const float* __restrict__ qmw,
                             const float* __restrict__ w1, const float* __restrict__ b1,
                             const float* __restrict__ w2, const float* __restrict__ b2,
                             const float* __restrict__ w3, const float* __restrict__ b3) {
    __shared__ float s_h1[16], s_h2[16], s_nr[18], s_coef[16];
    const int t = threadIdx.x;  // 0..63

    if (t < 16) s_h1[t] = gelu_exact(noise[0] * w1[t] + b1[t]);
    __syncthreads();
    if (t < 16) {
        float s = b2[t];
#pragma unroll
        for (int j = 0; j < 16; j++) s += s_h1[j] * w2[j * 16 + t];
        s_h2[t] = gelu_exact(s);
    }
    __syncthreads();
    if (t < 18) {
        float s = b3[t];
#pragma unroll
        for (int j = 0; j < 16; j++) s += s_h2[j] * w3[j * 18 + t];
        s_nr[t] = s;
    }
    __syncthreads();
    if (t == 0) {
        float wmax = qmw[0];
#pragma unroll
        for (int i = 1; i < 16; i++) wmax = fmaxf(wmax, qmw[i]);
        float esum = 0.0f;
#pragma unroll
        for (int i = 0; i < 16; i++) esum += expf(qmw[i] - wmax);
        float inv = 1.0f / esum;
        float nr0 = s_nr[0], nr1 = s_nr[1];
#pragma unroll
        for (int i = 0; i < 16; i++)
            s_coef[i] = (expf(qmw[i] - wmax) * inv * nr0 + nr1) * s_nr[2 + i];
    }
    __syncthreads();
    {
        float acc = 0.0f;
#pragma unroll
        for (int i = 0; i < 16; i++) acc += s_coef[i] * qmat[i * 64 + t];
        g_lq[t] = acc;
    }
    // allow the PDL-gated main kernel to proceed as soon as g_lq is visible
    __threadfence();
    cudaTriggerProgrammaticLaunchCompletion();
}

// ---------------------------------------------------------------------------
// Main kernel: R6's measured-fastest body (80.3us, 168 regs), PDL-gated.
// Order: issue the 16 independent x-loads FIRST (they overlap the setup
// kernel), then cudaGridDependencySynchronize(), then read g_lq.
// No __launch_bounds__ cap (R8/R9: caps => spills/slower); xv[64] stays
// in registers (R11: any re-read scheme gets hoisted by ptxas -> 190 regs).
// ---------------------------------------------------------------------------
__global__ void __launch_bounds__(128)
dct_kernel(const float* __restrict__ x,
           float* __restrict__ lo,
           float* __restrict__ hi) {
    constexpr DCTTab CD = make_dct();

    __shared__ __align__(16) float sq[64];

    const int t   = threadIdx.x;
    const int b   = blockIdx.x * 128 + t;       // global 8x8-block id
    const int img = b >> 6;
    const int by  = (b >> 3) & 7;
    const int bx  = b & 7;
    const long base = (long)img * 4096 + by * 512 + bx * 8;  // floats

    // ---- load 8x8 block (independent of setup; overlaps it under PDL) ----
    float xv[64];
#pragma unroll
    for (int r = 0; r < 8; r++) {
        const float4* p = reinterpret_cast<const float4*>(x + base + r * 64);
        float4 a = p[0], c = p[1];
        xv[r * 8 + 0] = a.x; xv[r * 8 + 1] = a.y; xv[r * 8 + 2] = a.z; xv[r * 8 + 3] = a.w;
        xv[r * 8 + 4] = c.x; xv[r * 8 + 5] = c.y; xv[r * 8 + 6] = c.z; xv[r * 8 + 7] = c.w;
    }

    // ---- wait for setup_kernel's g_lq, then stage it in smem ----
    cudaGridDependencySynchronize();
    if (t < 64) sq[t] = g_lq[t];
    __syncthreads();

    // ---- row DCT: W[r][m] = sum_j x[r][j] * C[m][j] ----
    float w[64];
#pragma unroll
    for (int r = 0; r < 8; r++) {
#pragma unroll
        for (int m = 0; m < 8; m++) {
            float acc = 0.0f;
#pragma unroll
            for (int j = 0; j < 8; j++) acc = fmaf(xv[r * 8 + j], CD.v[m][j], acc);
            w[r * 8 + m] = acc;
        }
    }

    // ---- col DCT in place ----
#pragma unroll
    for (int c = 0; c < 8; c++) {
        float y[8];
#pragma unroll
        for (int r = 0; r < 8; r++) y[r] = w[r * 8 + c];
#pragma unroll
        for (int i = 0; i < 8; i++) {
            float acc = 0.0f;
#pragma unroll
            for (int r = 0; r < 8; r++) acc = fmaf(y[r], CD.v[i][r], acc);
            w[i * 8 + c] = acc;
        }
    }

    // ---- spectral mask (warp-uniform float4 smem broadcasts) ----
    const float4* sq4 = reinterpret_cast<const float4*>(sq);
#pragma unroll
    for (int k = 0; k < 16; k++) {
        float4 q = sq4[k];
        w[k * 4 + 0] *= q.x;
        w[k * 4 + 1] *= q.y;
        w[k * 4 + 2] *= q.z;
        w[k * 4 + 3] *= q.w;
    }

    // ---- col IDCT in place ----
#pragma unroll
    for (int c = 0; c < 8; c++) {
        float z[8];
#pragma unroll
        for (int i = 0; i < 8; i++) z[i] = w[i * 8 + c];
#pragma unroll
        for (int a = 0; a < 8; a++) {
            float acc = 0.0f;
#pragma unroll
            for (int i = 0; i < 8; i++) acc = fmaf(z[i], CD.v[i][a], acc);
            w[a * 8 + c] = acc;
        }
    }

    // ---- row IDCT + high = x - low + stores ----
#pragma unroll
    for (int r = 0; r < 8; r++) {
        float tt[8];
#pragma unroll
        for (int m = 0; m < 8; m++) tt[m] = w[r * 8 + m];

        float lv[8], hv[8];
#pragma unroll
        for (int bb = 0; bb < 8; bb++) {
            float acc = 0.0f;
#pragma unroll
            for (int m = 0; m < 8; m++) acc = fmaf(tt[m], CD.v[m][bb], acc);
            lv[bb] = acc;
            hv[bb] = xv[r * 8 + bb] - acc;
        }

        float4* lp = reinterpret_cast<float4*>(lo + base + r * 64);
        lp[0] = make_float4(lv[0], lv[1], lv[2], lv[3]);
        lp[1] = make_float4(lv[4], lv[5], lv[6], lv[7]);
        float4* hp = reinterpret_cast<float4*>(hi + base + r * 64);
        hp[0] = make_float4(hv[0], hv[1], hv[2], hv[3]);
        hp[1] = make_float4(hv[4], hv[5], hv[6], hv[7]);
    }
}

// ---------------------------------------------------------------------------
// Launch: metadata order = x, noise_level, qmat, qmat_weights, w1,b1,w2,b2,w3,b3
// d_out = [low (N floats) | high (N floats)]
// Main kernel is launched with programmatic stream serialization (PDL) so
// its launch + leading x-loads overlap setup_kernel.
// ---------------------------------------------------------------------------
extern "C" void kernel_launch(void* const* d_in, const int* in_sizes, int n_in,
                              void* d_out, int out_size) {
    const float* x     = (const float*)d_in[0];
    const float* noise = (const float*)d_in[1];
    const float* qmat  = (const float*)d_in[2];
    const float* qmw   = (const float*)d_in[3];
    const float* w1    = (const float*)d_in[4];
    const float* b1    = (const float*)d_in[5];
    const float* w2    = (const float*)d_in[6];
    const float* b2    = (const float*)d_in[7];
    const float* w3    = (const float*)d_in[8];
    const float* b3    = (const float*)d_in[9];

    const int N       = in_sizes[0];   // 33554432
    const int nblocks = N / 64;        // 524288 8x8 blocks
    const int grid    = nblocks / 128;

    float* lo = (float*)d_out;
    float* hi = lo + N;

    setup_kernel<<<1, 64>>>(noise, qmat, qmw, w1, b1, w2, b2, w3, b3);

    cudaLaunchConfig_t cfg = {};
    cfg.gridDim  = dim3(grid, 1, 1);
    cfg.blockDim = dim3(128, 1, 1);
    cfg.dynamicSmemBytes = 0;
    cfg.stream = 0;
    cudaLaunchAttribute attr[1];
    attr[0].id = cudaLaunchAttributeProgrammaticStreamSerialization;
    attr[0].val.programmaticStreamSerializationAllowed = 1;
    cfg.attrs = attr;
    cfg.numAttrs = 1;
    cudaLaunchKernelEx(&cfg, dct_kernel, x, lo, hi);
}